// round 14
// baseline (speedup 1.0000x reference)
#include <cuda_runtime.h>
#include <cmath>
#include <cstdint>

static constexpr int H = 512, W = 512, BATCH = 8;
static constexpr int NPIX = H * W;
static constexpr int NXi = BATCH * 3 * NPIX;          // 6,291,456
static constexpr int NFEAT = BATCH * 32 * NPIX;       // 67,108,864
static constexpr int MAXB = 10;                       // int(b) <= 10 always
static constexpr int UBLOCKS = 1024;
static constexpr int PBLOCKS = 8192;                  // conv1b grid size

__device__ float g_x1[NFEAT];
__device__ float g_x1b[NFEAT];
__device__ float g_x2[NFEAT];
__device__ float g_x2b[NFEAT];
__device__ float g_x3[NFEAT];
__device__ float g_x3b[NFEAT];
__device__ float g_U4[2 * 36864];     // F(4x4,3x3) transformed w2, w3
__device__ float g_part[PBLOCKS];
__device__ float g_sum[MAXB + 2];
__device__ float g_n3;
__device__ int   g_b;

// ---------------------------------------------------------------------------
__global__ void reduce2_k(int n) {
    float s = 0.f;
    for (int i = threadIdx.x; i < n; i += 256) s += g_part[i];
#pragma unroll
    for (int o = 16; o; o >>= 1) s += __shfl_xor_sync(0xffffffffu, s, o);
    __shared__ float ws[8];
    if ((threadIdx.x & 31) == 0) ws[threadIdx.x >> 5] = s;
    __syncthreads();
    if (threadIdx.x == 0) {
        float t = 0.f;
#pragma unroll
        for (int i = 0; i < 8; i++) t += ws[i];
        g_sum[0] = t;
    }
}

__global__ void params_k() {
    float m32 = g_sum[0] / (float)NXi;
    double xx1 = (double)m32;
    double s = xx1 * xx1;
    double n3 = -0.79 * s + 0.81 * xx1 + 1.4;
    double bf;
    if (xx1 < 0.1)       bf = -25.0 * xx1 + 10.0;
    else if (xx1 < 0.45) bf = 17.14 * s - 15.14 * xx1 + 10.0;
    else                 bf = 5.66 * s - 2.93 * xx1 + 7.2;
    g_n3 = (float)n3;
    int b = (int)bf;
    if (b > MAXB) b = MAXB;
    g_b = b;
}

// ---------------------------------------------------------------------------
// F(4x4,3x3) weight transform: U = G g G^T (round-12 proven).
// U4[sel][ (i*6+j)*1024 + cin*32 + cout ].
// ---------------------------------------------------------------------------
__global__ void wino_wt4_k(const float* __restrict__ w2,
                           const float* __restrict__ w3) {
    const float* w = blockIdx.x ? w3 : w2;
    float* U = g_U4 + blockIdx.x * 36864;
    const float f6 = 1.f / 6.f, f12 = 1.f / 12.f, f24 = 1.f / 24.f;
    int t = threadIdx.x;
    int cout = t >> 5, cin = t & 31;
    float g[9];
#pragma unroll
    for (int i = 0; i < 9; i++) g[i] = w[(cout * 32 + cin) * 9 + i];
    float T[6][3];
#pragma unroll
    for (int c = 0; c < 3; c++) {
        float g0 = g[c], g1 = g[3 + c], g2 = g[6 + c];
        T[0][c] = 0.25f * g0;
        T[1][c] = -f6 * (g0 + g1 + g2);
        T[2][c] = f6 * (-g0 + g1 - g2);
        T[3][c] = f24 * g0 + f12 * g1 + f6 * g2;
        T[4][c] = f24 * g0 - f12 * g1 + f6 * g2;
        T[5][c] = g2;
    }
#pragma unroll
    for (int i = 0; i < 6; i++) {
        float t0 = T[i][0], t1 = T[i][1], t2 = T[i][2];
        float u[6];
        u[0] = 0.25f * t0;
        u[1] = -f6 * (t0 + t1 + t2);
        u[2] = f6 * (-t0 + t1 - t2);
        u[3] = f24 * t0 + f12 * t1 + f6 * t2;
        u[4] = f24 * t0 - f12 * t1 + f6 * t2;
        u[5] = t2;
#pragma unroll
        for (int j = 0; j < 6; j++)
            U[(i * 6 + j) * 1024 + cin * 32 + cout] = u[j];
    }
}

#define BT6(o0, o1, o2, o3, o4, o5, d0, d1, d2, d3, d4, d5) do {             \
        o0 = 4.f * d0 - 5.f * d2 + d4;                                       \
        o1 = -4.f * d1 - 4.f * d2 + d3 + d4;                                 \
        o2 = 4.f * d1 - 4.f * d2 - d3 + d4;                                  \
        o3 = -2.f * d1 - d2 + 2.f * d3 + d4;                                 \
        o4 = 2.f * d1 - d2 - 2.f * d3 + d4;                                  \
        o5 = 4.f * d1 - 5.f * d3 + d5;                                       \
    } while (0)

// ---------------------------------------------------------------------------
// Fused Winograd F(4x4,3x3) conv 32->32, bias+relu (round-12 proven, exact).
// Block 576 thr, 2 sub-tiles of 64x * 4y px. 8 phases x 4 cins.
// ---------------------------------------------------------------------------
__global__ void __launch_bounds__(576, 2) wino4_k(
    const float* __restrict__ in, int usel,
    const float* __restrict__ bg, float* __restrict__ out)
{
    extern __shared__ float sm[];
    float* raw = sm;                  // 32 * 408
    float* T   = sm + 13056;          // 4 * 600
    float* V   = sm + 15456;          // 2 * 2304
    float* M   = sm;                  // alias, 36 * 576

    const int t = threadIdx.x;
    const int y0 = blockIdx.y << 2, bb = blockIdx.z;

    const int xc = t / 96;
    const int xrem = t - xc * 96;
    const int xtile = xrem / 6, xj = xrem - xtile * 6;
    const bool xact = (t < 384);

    const int p  = t >> 4;
    const int kk = t & 15;
    const int cg = kk & 3;
    const int tg = kk >> 2;
    const float* Ub = g_U4 + usel * 36864 + p * 1024 + cg * 8;

    const int eco = t & 31, etl = (t >> 5) & 15;
    const float bv = __ldg(&bg[eco]);
    float* plane = out + ((size_t)(bb * 32 + eco)) * NPIX;
    const float* inb = in + (size_t)bb * 32 * NPIX;

#define STAGE1(g) do { if (xact) {                                           \
        const float* dp = raw + ((g) * 4 + xc) * 408 + xtile * 4 + xj;       \
        float d0 = dp[0], d1 = dp[68], d2 = dp[136];                         \
        float d3 = dp[204], d4 = dp[272], d5 = dp[340];                      \
        float* tp = T + xc * 600 + xtile * 37 + xj;                          \
        float o0, o1, o2, o3, o4, o5;                                        \
        BT6(o0, o1, o2, o3, o4, o5, d0, d1, d2, d3, d4, d5);                 \
        tp[0] = o0; tp[6] = o1; tp[12] = o2;                                 \
        tp[18] = o3; tp[24] = o4; tp[30] = o5;                               \
    } } while (0)

#define STAGE2(g) do { if (xact) {                                           \
        const float* tp = T + xc * 600 + xtile * 37 + xj * 6;                \
        float d0 = tp[0], d1 = tp[1], d2 = tp[2];                            \
        float d3 = tp[3], d4 = tp[4], d5 = tp[5];                            \
        float* vb = V + ((g) & 1) * 2304 + xc * 576 + xj * 96 + xtile;       \
        float o0, o1, o2, o3, o4, o5;                                        \
        BT6(o0, o1, o2, o3, o4, o5, d0, d1, d2, d3, d4, d5);                 \
        vb[0] = o0; vb[16] = o1; vb[32] = o2;                                \
        vb[48] = o3; vb[64] = o4; vb[80] = o5;                               \
    } } while (0)

#pragma unroll 1
    for (int tix = 0; tix < 2; ++tix) {
        const int x0 = ((blockIdx.x << 1) + tix) << 6;

        for (int i = t; i < 32 * 396; i += 576) {
            int cin = i / 396, rem = i - cin * 396;
            int r = rem / 66, c = rem - r * 66;
            int gy = y0 - 1 + r, gx = x0 - 1 + c;
            float v = 0.f;
            if ((unsigned)gy < (unsigned)H && (unsigned)gx < (unsigned)W)
                v = inb[(size_t)cin * NPIX + gy * W + gx];
            raw[cin * 408 + r * 68 + c] = v;
        }
        __syncthreads();

        float acc[8][4];
#pragma unroll
        for (int i = 0; i < 8; i++)
#pragma unroll
            for (int j = 0; j < 4; j++) acc[i][j] = 0.f;

        STAGE1(0);
        __syncthreads();
        STAGE2(0);
        __syncthreads();

#pragma unroll 1
        for (int g = 0; g < 8; ++g) {
            if (g < 7) STAGE1(g + 1);
            {
                const float* vb = V + (g & 1) * 2304 + p * 16 + tg * 4;
                const float* ub = Ub + g * 128;
#pragma unroll
                for (int cc = 0; cc < 4; ++cc) {
                    float4 u0 = __ldg(reinterpret_cast<const float4*>(ub + cc * 32));
                    float4 u1 = __ldg(reinterpret_cast<const float4*>(ub + cc * 32 + 4));
                    float4 v = *reinterpret_cast<const float4*>(vb + cc * 576);
                    float ua[8] = {u0.x, u0.y, u0.z, u0.w, u1.x, u1.y, u1.z, u1.w};
                    float va[4] = {v.x, v.y, v.z, v.w};
#pragma unroll
                    for (int c = 0; c < 8; c++) {
                        acc[c][0] = fmaf(ua[c], va[0], acc[c][0]);
                        acc[c][1] = fmaf(ua[c], va[1], acc[c][1]);
                        acc[c][2] = fmaf(ua[c], va[2], acc[c][2]);
                        acc[c][3] = fmaf(ua[c], va[3], acc[c][3]);
                    }
                }
            }
            __syncthreads();
            if (g < 7) STAGE2(g + 1);
            __syncthreads();
        }

#pragma unroll
        for (int ti = 0; ti < 4; ++ti) {
            float* mp = M + p * 576 + (tg * 4 + ti) * 36 + cg * 8;
            *reinterpret_cast<float4*>(mp) =
                make_float4(acc[0][ti], acc[1][ti], acc[2][ti], acc[3][ti]);
            *reinterpret_cast<float4*>(mp + 4) =
                make_float4(acc[4][ti], acc[5][ti], acc[6][ti], acc[7][ti]);
        }
        __syncthreads();

        if (t < 512) {
            const float* mb = M + etl * 36 + eco;
            float P[4][6];
#pragma unroll
            for (int j = 0; j < 6; ++j) {
                float c0 = mb[j * 576];
                float c1 = mb[(6 + j) * 576];
                float c2 = mb[(12 + j) * 576];
                float c3 = mb[(18 + j) * 576];
                float c4 = mb[(24 + j) * 576];
                float c5 = mb[(30 + j) * 576];
                P[0][j] = c0 + c1 + c2 + c3 + c4;
                P[1][j] = c1 - c2 + 2.f * c3 - 2.f * c4;
                P[2][j] = c1 + c2 + 4.f * c3 + 4.f * c4;
                P[3][j] = c1 - c2 + 8.f * c3 - 8.f * c4 + c5;
            }
            float* ob = plane + (size_t)y0 * W + x0 + etl * 4;
#pragma unroll
            for (int a = 0; a < 4; ++a) {
                float p0 = P[a][0], p1 = P[a][1], p2 = P[a][2];
                float p3 = P[a][3], p4 = P[a][4], p5 = P[a][5];
                float4 y;
                y.x = fmaxf(p0 + p1 + p2 + p3 + p4 + bv, 0.f);
                y.y = fmaxf(p1 - p2 + 2.f * p3 - 2.f * p4 + bv, 0.f);
                y.z = fmaxf(p1 + p2 + 4.f * p3 + 4.f * p4 + bv, 0.f);
                y.w = fmaxf(p1 - p2 + 8.f * p3 - 8.f * p4 + p5 + bv, 0.f);
                *reinterpret_cast<float4*>(ob + (size_t)a * W) = y;
            }
        }
        __syncthreads();
    }
#undef STAGE1
#undef STAGE2
}

// ---------------------------------------------------------------------------
// conv1 BOTH branches + block partial sums of x (round-13 piece, kept).
// ---------------------------------------------------------------------------
__global__ void __launch_bounds__(256) conv1b_k(
    const float* __restrict__ in, const float* __restrict__ wg,
    const float* __restrict__ bg, float* __restrict__ out0,
    float* __restrict__ out1)
{
    __shared__ float w_s[3 * 9 * 32];
    __shared__ float sums[9 * 32];
    __shared__ float tile[10 * 35];
    const int t  = threadIdx.x;
    const int tg = t >> 6;
    const int pt = t & 63;
    const int lx = (pt & 7) << 2;
    const int ly = pt >> 3;
    const int bx = blockIdx.x << 5;
    const int by = blockIdx.y << 3;
    const int bb = blockIdx.z;

    for (int i = t; i < 3 * 9 * 32; i += 256) {
        int cout = i & 31;
        int rem  = i >> 5;
        int cin  = rem / 9, tap = rem - cin * 9;
        w_s[cin * 288 + tap * 32 + cout] = wg[(cout * 3 + cin) * 9 + tap];
    }
    __syncthreads();
    if (t < 32) {
        float TS = 0, R0 = 0, R2 = 0, C0 = 0, C2 = 0;
        float Wa = 0, Wb = 0, Wc = 0, Wd = 0;
        for (int cin = 0; cin < 3; ++cin) {
            const float* wb = &w_s[cin * 288];
            float w[9];
#pragma unroll
            for (int k = 0; k < 9; ++k) w[k] = wb[k * 32 + t];
            TS += w[0] + w[1] + w[2] + w[3] + w[4] + w[5] + w[6] + w[7] + w[8];
            R0 += w[0] + w[1] + w[2];
            R2 += w[6] + w[7] + w[8];
            C0 += w[0] + w[3] + w[6];
            C2 += w[2] + w[5] + w[8];
            Wa += w[0]; Wb += w[2]; Wc += w[6]; Wd += w[8];
        }
        sums[t]        = TS;
        sums[32 + t]   = R0;
        sums[64 + t]   = R2;
        sums[96 + t]   = C0;
        sums[128 + t]  = C2;
        sums[160 + t]  = Wa;
        sums[192 + t]  = Wb;
        sums[224 + t]  = Wc;
        sums[256 + t]  = Wd;
    }

    float acc[8][4];
#pragma unroll
    for (int c = 0; c < 8; c++)
#pragma unroll
        for (int pp = 0; pp < 4; pp++) acc[c][pp] = 0.f;

    const float* inb = in + (size_t)bb * 3 * NPIX;

    for (int cin = 0; cin < 3; ++cin) {
        __syncthreads();
        const float* ip = inb + (size_t)cin * NPIX;
        for (int i = t; i < 340; i += 256) {
            int r = i / 34, c = i - r * 34;
            int gy = by - 1 + r, gx = bx - 1 + c;
            float v = 0.f;
            if ((unsigned)gy < (unsigned)H && (unsigned)gx < (unsigned)W)
                v = ip[gy * W + gx];
            tile[r * 35 + c] = v;
        }
        __syncthreads();
        const float* wb = &w_s[cin * 288 + tg * 8];
#pragma unroll
        for (int ky = 0; ky < 3; ++ky) {
            float iv[6];
#pragma unroll
            for (int jj = 0; jj < 6; ++jj) iv[jj] = tile[(ly + ky) * 35 + lx + jj];
#pragma unroll
            for (int kx = 0; kx < 3; ++kx) {
                const float* wv = wb + (ky * 3 + kx) * 32;
#pragma unroll
                for (int c = 0; c < 8; ++c) {
                    float wf = wv[c];
#pragma unroll
                    for (int pp = 0; pp < 4; ++pp)
                        acc[c][pp] = fmaf(iv[kx + pp], wf, acc[c][pp]);
                }
            }
        }
    }

    const int oy = by + ly, ox0 = bx + lx;
    const bool top = (oy == 0), bot = (oy == H - 1);
#pragma unroll
    for (int c = 0; c < 8; ++c) {
        int cout = tg * 8 + c;
        float bvv = bg[cout];
        float base = sums[cout];
        if (top) base -= sums[32 + cout];
        if (bot) base -= sums[64 + cout];
        float4 o0, o1;
        float* p0 = &o0.x;
        float* p1 = &o1.x;
#pragma unroll
        for (int pp = 0; pp < 4; ++pp) {
            int ox = ox0 + pp;
            float loc = base;
            if (ox == 0) {
                loc -= sums[96 + cout];
                if (top) loc += sums[160 + cout];
                if (bot) loc += sums[224 + cout];
            }
            if (ox == W - 1) {
                loc -= sums[128 + cout];
                if (top) loc += sums[192 + cout];
                if (bot) loc += sums[256 + cout];
            }
            p0[pp] = fmaxf(acc[c][pp] + bvv, 0.f);
            p1[pp] = fmaxf(loc - acc[c][pp] + bvv, 0.f);
        }
        size_t off = ((size_t)(bb * 32 + cout)) * NPIX + (size_t)oy * W + ox0;
        *reinterpret_cast<float4*>(&out0[off]) = o0;
        *reinterpret_cast<float4*>(&out1[off]) = o1;
    }

    // ---- partial sum of x over this block's tile ----
    float s = 0.f;
    if (tg == 0) {
#pragma unroll
        for (int cin = 0; cin < 3; ++cin) {
            const float4 v = *reinterpret_cast<const float4*>(
                inb + (size_t)cin * NPIX + (size_t)oy * W + ox0);
            s += (v.x + v.y) + (v.z + v.w);
        }
    }
#pragma unroll
    for (int o = 16; o; o >>= 1) s += __shfl_xor_sync(0xffffffffu, s, o);
    __shared__ float ws[8];
    if ((t & 31) == 0) ws[t >> 5] = s;
    __syncthreads();
    if (t == 0) {
        float tt = 0.f;
#pragma unroll
        for (int i = 0; i < 8; i++) tt += ws[i];
        g_part[blockIdx.x + (blockIdx.y << 4) + (blockIdx.z << 10)] = tt;
    }
}

// ---------------------------------------------------------------------------
// conv7 BOTH branches fused (round-13 piece, kept):
// x_r = 0.5*tanh(conv_br0+b) + 0.5*tanh(conv_br1+b).
// ---------------------------------------------------------------------------
__global__ void __launch_bounds__(256) conv7d_k(
    const float* __restrict__ x1, const float* __restrict__ x3,
    const float* __restrict__ x1b, const float* __restrict__ x3b,
    const float* __restrict__ wg, const float* __restrict__ bg,
    float* __restrict__ out)
{
    __shared__ float w_s[64 * 9 * 3];
    __shared__ float tile[34 * 35];
    const int t  = threadIdx.x;
    const int lx = (t & 7) << 2;
    const int ly = t >> 3;
    const int bx = blockIdx.x << 5;
    const int by = blockIdx.y << 5;
    const int bb = blockIdx.z;

    for (int i = t; i < 64 * 9 * 3; i += 256) {
        int cout = i % 3;
        int rem  = i / 3;
        int cin  = rem / 9, tap = rem - cin * 9;
        w_s[i] = wg[(cout * 64 + cin) * 9 + tap];
    }

    float acc[2][3][4];
#pragma unroll
    for (int b = 0; b < 2; b++)
#pragma unroll
        for (int c = 0; c < 3; c++)
#pragma unroll
            for (int pp = 0; pp < 4; pp++) acc[b][c][pp] = 0.f;

    for (int cin = 0; cin < 128; ++cin) {
        const int lc = cin & 63;
        const int br = cin >> 6;
        const float* ip;
        if (cin < 32)       ip = x1  + ((size_t)(bb * 32 + cin)) * NPIX;
        else if (cin < 64)  ip = x3  + ((size_t)(bb * 32 + cin - 32)) * NPIX;
        else if (cin < 96)  ip = x1b + ((size_t)(bb * 32 + cin - 64)) * NPIX;
        else                ip = x3b + ((size_t)(bb * 32 + cin - 96)) * NPIX;
        __syncthreads();
        for (int i = t; i < 34 * 34; i += 256) {
            int r = i / 34, c = i - r * 34;
            int gy = by - 1 + r, gx = bx - 1 + c;
            tile[r * 35 + c] =
                ((unsigned)gy < (unsigned)H && (unsigned)gx < (unsigned)W)
                    ? ip[gy * W + gx] : 0.f;
        }
        __syncthreads();
        const float* wb = &w_s[lc * 27];
#pragma unroll
        for (int ky = 0; ky < 3; ++ky) {
            float iv[6];
#pragma unroll
            for (int jj = 0; jj < 6; ++jj) iv[jj] = tile[(ly + ky) * 35 + lx + jj];
#pragma unroll
            for (int kx = 0; kx < 3; ++kx) {
                const float* wv = wb + (ky * 3 + kx) * 3;
#pragma unroll
                for (int c = 0; c < 3; ++c) {
                    float wf = wv[c];
#pragma unroll
                    for (int pp = 0; pp < 4; ++pp)
                        acc[br][c][pp] = fmaf(iv[kx + pp], wf, acc[br][c][pp]);
                }
            }
        }
    }

    const int oy = by + ly, ox = bx + lx;
#pragma unroll
    for (int c = 0; c < 3; ++c) {
        float bv = bg[c];
        float4 o;
        o.x = 0.5f * tanhf(acc[0][c][0] + bv) + 0.5f * tanhf(acc[1][c][0] + bv);
        o.y = 0.5f * tanhf(acc[0][c][1] + bv) + 0.5f * tanhf(acc[1][c][1] + bv);
        o.z = 0.5f * tanhf(acc[0][c][2] + bv) + 0.5f * tanhf(acc[1][c][2] + bv);
        o.w = 0.5f * tanhf(acc[0][c][3] + bv) + 0.5f * tanhf(acc[1][c][3] + bv);
        *reinterpret_cast<float4*>(
            &out[((size_t)(bb * 3 + c)) * NPIX + oy * W + ox]) = o;
    }
}

// ---------------------------------------------------------------------------
// Fused refinement update (round-4 proven).
// ---------------------------------------------------------------------------
__global__ void update_k(const float4* __restrict__ xin, float4* __restrict__ x,
                         const float4* __restrict__ xr, int it, int first)
{
    const bool active = it < g_b;
    if (!active && !first) return;
    float m  = g_sum[it] * (1.0f / (float)NXi);
    float cf = (0.63f - m) / (g_n3 - m);
    const int n4 = NXi / 4;
    float s = 0.f;
    for (int i = blockIdx.x * 512 + threadIdx.x; i < n4; i += gridDim.x * 512) {
        float4 xv = first ? xin[i] : x[i];
        if (active) {
            float4 rv = xr[i];
            xv.x += rv.x * (xv.x * xv.x - xv.x) * cf;
            xv.y += rv.y * (xv.y * xv.y - xv.y) * cf;
            xv.z += rv.z * (xv.z * xv.z - xv.z) * cf;
            xv.w += rv.w * (xv.w * xv.w - xv.w) * cf;
            x[i] = xv;
        } else {
            x[i] = xv;
        }
        s += (xv.x + xv.y) + (xv.z + xv.w);
    }
#pragma unroll
    for (int o = 16; o; o >>= 1) s += __shfl_xor_sync(0xffffffffu, s, o);
    __shared__ float ws[16];
    if ((threadIdx.x & 31) == 0) ws[threadIdx.x >> 5] = s;
    __syncthreads();
    if (threadIdx.x < 32) {
        s = (threadIdx.x < 16) ? ws[threadIdx.x] : 0.f;
#pragma unroll
        for (int o = 8; o; o >>= 1) s += __shfl_xor_sync(0xffffffffu, s, o);
        if (threadIdx.x == 0) g_part[blockIdx.x] = s;
    }
}

__global__ void finalize_k(int it) {
    if (it >= g_b) return;
    float s = 0.f;
    for (int i = threadIdx.x; i < UBLOCKS; i += 256) s += g_part[i];
#pragma unroll
    for (int o = 16; o; o >>= 1) s += __shfl_xor_sync(0xffffffffu, s, o);
    __shared__ float ws[8];
    if ((threadIdx.x & 31) == 0) ws[threadIdx.x >> 5] = s;
    __syncthreads();
    if (threadIdx.x == 0) {
        float t = 0.f;
#pragma unroll
        for (int i = 0; i < 8; i++) t += ws[i];
        g_sum[it + 1] = t;
    }
}

// ---------------------------------------------------------------------------
static constexpr int WINO4_SMEM = 20736 * 4;   // 82,944 B

extern "C" void kernel_launch(void* const* d_in, const int* in_sizes, int n_in,
                              void* d_out, int out_size)
{
    const float* x  = (const float*)d_in[0];
    const float* w1 = (const float*)d_in[1];
    const float* b1 = (const float*)d_in[2];
    const float* w2 = (const float*)d_in[3];
    const float* b2 = (const float*)d_in[4];
    const float* w3 = (const float*)d_in[5];
    const float* b3 = (const float*)d_in[6];
    const float* w7 = (const float*)d_in[7];
    const float* b7 = (const float*)d_in[8];

    float* xo = (float*)d_out;      // final x
    float* xr = xo + NXi;           // x_r

    float *px1, *px1b, *px2, *px2b, *px3, *px3b;
    cudaGetSymbolAddress((void**)&px1, g_x1);
    cudaGetSymbolAddress((void**)&px1b, g_x1b);
    cudaGetSymbolAddress((void**)&px2, g_x2);
    cudaGetSymbolAddress((void**)&px2b, g_x2b);
    cudaGetSymbolAddress((void**)&px3, g_x3);
    cudaGetSymbolAddress((void**)&px3b, g_x3b);

    cudaFuncSetAttribute(wino4_k, cudaFuncAttributeMaxDynamicSharedMemorySize,
                         WINO4_SMEM);

    dim3 cg1(16, 64, 8);       // conv1: 32x8 px tiles, 256 thr (8192 blocks)
    dim3 cgw(4, 128, 8);       // wino4: single branch, 576 thr
    dim3 cg7(16, 16, 8);       // conv7d: 32x32 px tiles, 256 thr

    // Order: wino4 layer2-branch0 is the 4th launch (ncu capture slot).
    wino_wt4_k<<<2, 1024>>>(w2, w3);                            // 1
    conv1b_k<<<cg1, 256>>>(x, w1, b1, px1, px1b);               // 2 (+ x sums)
    reduce2_k<<<1, 256>>>(PBLOCKS);                             // 3
    wino4_k<<<cgw, 576, WINO4_SMEM>>>(px1, 0, b2, px2);         // 4 <- profiled
    wino4_k<<<cgw, 576, WINO4_SMEM>>>(px2, 1, b3, px3);         // 5
    wino4_k<<<cgw, 576, WINO4_SMEM>>>(px1b, 0, b2, px2b);       // 6
    wino4_k<<<cgw, 576, WINO4_SMEM>>>(px2b, 1, b3, px3b);       // 7
    conv7d_k<<<cg7, 256>>>(px1, px3, px1b, px3b, w7, b7, xr);   // 8
    params_k<<<1, 1>>>();                                       // 9

    for (int it = 0; it < MAXB; ++it) {
        update_k<<<UBLOCKS, 512>>>((const float4*)x, (float4*)xo,
                                   (const float4*)xr, it, it == 0 ? 1 : 0);
        finalize_k<<<1, 256>>>(it);
    }
}

// round 15
// speedup vs baseline: 1.0424x; 1.0424x over previous
#include <cuda_runtime.h>
#include <cmath>
#include <cstdint>

static constexpr int H = 512, W = 512, BATCH = 8;
static constexpr int NPIX = H * W;
static constexpr int NXi = BATCH * 3 * NPIX;          // 6,291,456
static constexpr int NFEAT = BATCH * 32 * NPIX;       // 67,108,864
static constexpr int MAXB = 10;                       // int(b) <= 10 always
static constexpr int RBLOCKS = 512;
static constexpr int UBLOCKS = 1024;

__device__ float g_x1[NFEAT];
__device__ float g_x1b[NFEAT];
__device__ float g_x2[NFEAT];
__device__ float g_x3[NFEAT];
__device__ float g_U4[2 * 36864];     // F(4x4,3x3) transformed w2, w3
__device__ float g_part[UBLOCKS];
__device__ float g_sum[MAXB + 2];
__device__ float g_n3;
__device__ int   g_b;
__device__ unsigned g_cnt[MAXB + 1];  // zero-init; self-resetting per replay

// ---------------------------------------------------------------------------
// Initial mean reduction + params (round-12 proven)
// ---------------------------------------------------------------------------
__global__ void reduce1_k(const float* __restrict__ x) {
    const float4* x4 = reinterpret_cast<const float4*>(x);
    const int n4 = NXi / 4;
    float s = 0.f;
    for (int i = blockIdx.x * 256 + threadIdx.x; i < n4; i += gridDim.x * 256) {
        float4 v = x4[i];
        s += (v.x + v.y) + (v.z + v.w);
    }
#pragma unroll
    for (int o = 16; o; o >>= 1) s += __shfl_xor_sync(0xffffffffu, s, o);
    __shared__ float ws[8];
    if ((threadIdx.x & 31) == 0) ws[threadIdx.x >> 5] = s;
    __syncthreads();
    if (threadIdx.x < 32) {
        s = (threadIdx.x < 8) ? ws[threadIdx.x] : 0.f;
#pragma unroll
        for (int o = 4; o; o >>= 1) s += __shfl_xor_sync(0xffffffffu, s, o);
        if (threadIdx.x == 0) g_part[blockIdx.x] = s;
    }
}

__global__ void reduce2_k() {
    float s = 0.f;
    for (int i = threadIdx.x; i < RBLOCKS; i += 256) s += g_part[i];
#pragma unroll
    for (int o = 16; o; o >>= 1) s += __shfl_xor_sync(0xffffffffu, s, o);
    __shared__ float ws[8];
    if ((threadIdx.x & 31) == 0) ws[threadIdx.x >> 5] = s;
    __syncthreads();
    if (threadIdx.x == 0) {
        float t = 0.f;
#pragma unroll
        for (int i = 0; i < 8; i++) t += ws[i];
        g_sum[0] = t;
    }
}

__global__ void params_k() {
    float m32 = g_sum[0] / (float)NXi;
    double xx1 = (double)m32;
    double s = xx1 * xx1;
    double n3 = -0.79 * s + 0.81 * xx1 + 1.4;
    double bf;
    if (xx1 < 0.1)       bf = -25.0 * xx1 + 10.0;
    else if (xx1 < 0.45) bf = 17.14 * s - 15.14 * xx1 + 10.0;
    else                 bf = 5.66 * s - 2.93 * xx1 + 7.2;
    g_n3 = (float)n3;
    int b = (int)bf;
    if (b > MAXB) b = MAXB;
    g_b = b;
}

// ---------------------------------------------------------------------------
// F(4x4,3x3) weight transform (round-12 proven).
// ---------------------------------------------------------------------------
__global__ void wino_wt4_k(const float* __restrict__ w2,
                           const float* __restrict__ w3) {
    const float* w = blockIdx.x ? w3 : w2;
    float* U = g_U4 + blockIdx.x * 36864;
    const float f6 = 1.f / 6.f, f12 = 1.f / 12.f, f24 = 1.f / 24.f;
    int t = threadIdx.x;
    int cout = t >> 5, cin = t & 31;
    float g[9];
#pragma unroll
    for (int i = 0; i < 9; i++) g[i] = w[(cout * 32 + cin) * 9 + i];
    float T[6][3];
#pragma unroll
    for (int c = 0; c < 3; c++) {
        float g0 = g[c], g1 = g[3 + c], g2 = g[6 + c];
        T[0][c] = 0.25f * g0;
        T[1][c] = -f6 * (g0 + g1 + g2);
        T[2][c] = f6 * (-g0 + g1 - g2);
        T[3][c] = f24 * g0 + f12 * g1 + f6 * g2;
        T[4][c] = f24 * g0 - f12 * g1 + f6 * g2;
        T[5][c] = g2;
    }
#pragma unroll
    for (int i = 0; i < 6; i++) {
        float t0 = T[i][0], t1 = T[i][1], t2 = T[i][2];
        float u[6];
        u[0] = 0.25f * t0;
        u[1] = -f6 * (t0 + t1 + t2);
        u[2] = f6 * (-t0 + t1 - t2);
        u[3] = f24 * t0 + f12 * t1 + f6 * t2;
        u[4] = f24 * t0 - f12 * t1 + f6 * t2;
        u[5] = t2;
#pragma unroll
        for (int j = 0; j < 6; j++)
            U[(i * 6 + j) * 1024 + cin * 32 + cout] = u[j];
    }
}

#define BT6(o0, o1, o2, o3, o4, o5, d0, d1, d2, d3, d4, d5) do {             \
        o0 = 4.f * d0 - 5.f * d2 + d4;                                       \
        o1 = -4.f * d1 - 4.f * d2 + d3 + d4;                                 \
        o2 = 4.f * d1 - 4.f * d2 - d3 + d4;                                  \
        o3 = -2.f * d1 - d2 + 2.f * d3 + d4;                                 \
        o4 = 2.f * d1 - d2 - 2.f * d3 + d4;                                  \
        o5 = 4.f * d1 - 5.f * d3 + d5;                                       \
    } while (0)

// ---------------------------------------------------------------------------
// Fused Winograd F(4x4,3x3) conv 32->32, bias+relu (round-12 proven, exact).
// ---------------------------------------------------------------------------
__global__ void __launch_bounds__(576, 2) wino4_k(
    const float* __restrict__ in, int usel,
    const float* __restrict__ bg, float* __restrict__ out)
{
    extern __shared__ float sm[];
    float* raw = sm;                  // 32 * 408
    float* T   = sm + 13056;          // 4 * 600
    float* V   = sm + 15456;          // 2 * 2304
    float* M   = sm;                  // alias, 36 * 576

    const int t = threadIdx.x;
    const int y0 = blockIdx.y << 2, bb = blockIdx.z;

    const int xc = t / 96;
    const int xrem = t - xc * 96;
    const int xtile = xrem / 6, xj = xrem - xtile * 6;
    const bool xact = (t < 384);

    const int p  = t >> 4;
    const int kk = t & 15;
    const int cg = kk & 3;
    const int tg = kk >> 2;
    const float* Ub = g_U4 + usel * 36864 + p * 1024 + cg * 8;

    const int eco = t & 31, etl = (t >> 5) & 15;
    const float bv = __ldg(&bg[eco]);
    float* plane = out + ((size_t)(bb * 32 + eco)) * NPIX;
    const float* inb = in + (size_t)bb * 32 * NPIX;

#define STAGE1(g) do { if (xact) {                                           \
        const float* dp = raw + ((g) * 4 + xc) * 408 + xtile * 4 + xj;       \
        float d0 = dp[0], d1 = dp[68], d2 = dp[136];                         \
        float d3 = dp[204], d4 = dp[272], d5 = dp[340];                      \
        float* tp = T + xc * 600 + xtile * 37 + xj;                          \
        float o0, o1, o2, o3, o4, o5;                                        \
        BT6(o0, o1, o2, o3, o4, o5, d0, d1, d2, d3, d4, d5);                 \
        tp[0] = o0; tp[6] = o1; tp[12] = o2;                                 \
        tp[18] = o3; tp[24] = o4; tp[30] = o5;                               \
    } } while (0)

#define STAGE2(g) do { if (xact) {                                           \
        const float* tp = T + xc * 600 + xtile * 37 + xj * 6;                \
        float d0 = tp[0], d1 = tp[1], d2 = tp[2];                            \
        float d3 = tp[3], d4 = tp[4], d5 = tp[5];                            \
        float* vb = V + ((g) & 1) * 2304 + xc * 576 + xj * 96 + xtile;       \
        float o0, o1, o2, o3, o4, o5;                                        \
        BT6(o0, o1, o2, o3, o4, o5, d0, d1, d2, d3, d4, d5);                 \
        vb[0] = o0; vb[16] = o1; vb[32] = o2;                                \
        vb[48] = o3; vb[64] = o4; vb[80] = o5;                               \
    } } while (0)

#pragma unroll 1
    for (int tix = 0; tix < 2; ++tix) {
        const int x0 = ((blockIdx.x << 1) + tix) << 6;

        for (int i = t; i < 32 * 396; i += 576) {
            int cin = i / 396, rem = i - cin * 396;
            int r = rem / 66, c = rem - r * 66;
            int gy = y0 - 1 + r, gx = x0 - 1 + c;
            float v = 0.f;
            if ((unsigned)gy < (unsigned)H && (unsigned)gx < (unsigned)W)
                v = inb[(size_t)cin * NPIX + gy * W + gx];
            raw[cin * 408 + r * 68 + c] = v;
        }
        __syncthreads();

        float acc[8][4];
#pragma unroll
        for (int i = 0; i < 8; i++)
#pragma unroll
            for (int j = 0; j < 4; j++) acc[i][j] = 0.f;

        STAGE1(0);
        __syncthreads();
        STAGE2(0);
        __syncthreads();

#pragma unroll 1
        for (int g = 0; g < 8; ++g) {
            if (g < 7) STAGE1(g + 1);
            {
                const float* vb = V + (g & 1) * 2304 + p * 16 + tg * 4;
                const float* ub = Ub + g * 128;
#pragma unroll
                for (int cc = 0; cc < 4; ++cc) {
                    float4 u0 = __ldg(reinterpret_cast<const float4*>(ub + cc * 32));
                    float4 u1 = __ldg(reinterpret_cast<const float4*>(ub + cc * 32 + 4));
                    float4 v = *reinterpret_cast<const float4*>(vb + cc * 576);
                    float ua[8] = {u0.x, u0.y, u0.z, u0.w, u1.x, u1.y, u1.z, u1.w};
                    float va[4] = {v.x, v.y, v.z, v.w};
#pragma unroll
                    for (int c = 0; c < 8; c++) {
                        acc[c][0] = fmaf(ua[c], va[0], acc[c][0]);
                        acc[c][1] = fmaf(ua[c], va[1], acc[c][1]);
                        acc[c][2] = fmaf(ua[c], va[2], acc[c][2]);
                        acc[c][3] = fmaf(ua[c], va[3], acc[c][3]);
                    }
                }
            }
            __syncthreads();
            if (g < 7) STAGE2(g + 1);
            __syncthreads();
        }

#pragma unroll
        for (int ti = 0; ti < 4; ++ti) {
            float* mp = M + p * 576 + (tg * 4 + ti) * 36 + cg * 8;
            *reinterpret_cast<float4*>(mp) =
                make_float4(acc[0][ti], acc[1][ti], acc[2][ti], acc[3][ti]);
            *reinterpret_cast<float4*>(mp + 4) =
                make_float4(acc[4][ti], acc[5][ti], acc[6][ti], acc[7][ti]);
        }
        __syncthreads();

        if (t < 512) {
            const float* mb = M + etl * 36 + eco;
            float P[4][6];
#pragma unroll
            for (int j = 0; j < 6; ++j) {
                float c0 = mb[j * 576];
                float c1 = mb[(6 + j) * 576];
                float c2 = mb[(12 + j) * 576];
                float c3 = mb[(18 + j) * 576];
                float c4 = mb[(24 + j) * 576];
                float c5 = mb[(30 + j) * 576];
                P[0][j] = c0 + c1 + c2 + c3 + c4;
                P[1][j] = c1 - c2 + 2.f * c3 - 2.f * c4;
                P[2][j] = c1 + c2 + 4.f * c3 + 4.f * c4;
                P[3][j] = c1 - c2 + 8.f * c3 - 8.f * c4 + c5;
            }
            float* ob = plane + (size_t)y0 * W + x0 + etl * 4;
#pragma unroll
            for (int a = 0; a < 4; ++a) {
                float p0 = P[a][0], p1 = P[a][1], p2 = P[a][2];
                float p3 = P[a][3], p4 = P[a][4], p5 = P[a][5];
                float4 y;
                y.x = fmaxf(p0 + p1 + p2 + p3 + p4 + bv, 0.f);
                y.y = fmaxf(p1 - p2 + 2.f * p3 - 2.f * p4 + bv, 0.f);
                y.z = fmaxf(p1 + p2 + 4.f * p3 + 4.f * p4 + bv, 0.f);
                y.w = fmaxf(p1 - p2 + 8.f * p3 - 8.f * p4 + p5 + bv, 0.f);
                *reinterpret_cast<float4*>(ob + (size_t)a * W) = y;
            }
        }
        __syncthreads();
    }
#undef STAGE1
#undef STAGE2
}

// ---------------------------------------------------------------------------
// conv1 BOTH branches in one pass (round-10/12 proven).
// ---------------------------------------------------------------------------
__global__ void __launch_bounds__(256) conv1b_k(
    const float* __restrict__ in, const float* __restrict__ wg,
    const float* __restrict__ bg, float* __restrict__ out0,
    float* __restrict__ out1)
{
    __shared__ float w_s[3 * 9 * 32];
    __shared__ float sums[9 * 32];
    __shared__ float tile[10 * 35];
    const int t  = threadIdx.x;
    const int tg = t >> 6;
    const int pt = t & 63;
    const int lx = (pt & 7) << 2;
    const int ly = pt >> 3;
    const int bx = blockIdx.x << 5;
    const int by = blockIdx.y << 3;
    const int bb = blockIdx.z;

    for (int i = t; i < 3 * 9 * 32; i += 256) {
        int cout = i & 31;
        int rem  = i >> 5;
        int cin  = rem / 9, tap = rem - cin * 9;
        w_s[cin * 288 + tap * 32 + cout] = wg[(cout * 3 + cin) * 9 + tap];
    }
    __syncthreads();
    if (t < 32) {
        float TS = 0, R0 = 0, R2 = 0, C0 = 0, C2 = 0;
        float Wa = 0, Wb = 0, Wc = 0, Wd = 0;
        for (int cin = 0; cin < 3; ++cin) {
            const float* wb = &w_s[cin * 288];
            float w[9];
#pragma unroll
            for (int k = 0; k < 9; ++k) w[k] = wb[k * 32 + t];
            TS += w[0] + w[1] + w[2] + w[3] + w[4] + w[5] + w[6] + w[7] + w[8];
            R0 += w[0] + w[1] + w[2];
            R2 += w[6] + w[7] + w[8];
            C0 += w[0] + w[3] + w[6];
            C2 += w[2] + w[5] + w[8];
            Wa += w[0]; Wb += w[2]; Wc += w[6]; Wd += w[8];
        }
        sums[t]        = TS;
        sums[32 + t]   = R0;
        sums[64 + t]   = R2;
        sums[96 + t]   = C0;
        sums[128 + t]  = C2;
        sums[160 + t]  = Wa;
        sums[192 + t]  = Wb;
        sums[224 + t]  = Wc;
        sums[256 + t]  = Wd;
    }

    float acc[8][4];
#pragma unroll
    for (int c = 0; c < 8; c++)
#pragma unroll
        for (int pp = 0; pp < 4; pp++) acc[c][pp] = 0.f;

    const float* inb = in + (size_t)bb * 3 * NPIX;

    for (int cin = 0; cin < 3; ++cin) {
        __syncthreads();
        const float* ip = inb + (size_t)cin * NPIX;
        for (int i = t; i < 340; i += 256) {
            int r = i / 34, c = i - r * 34;
            int gy = by - 1 + r, gx = bx - 1 + c;
            float v = 0.f;
            if ((unsigned)gy < (unsigned)H && (unsigned)gx < (unsigned)W)
                v = ip[gy * W + gx];
            tile[r * 35 + c] = v;
        }
        __syncthreads();
        const float* wb = &w_s[cin * 288 + tg * 8];
#pragma unroll
        for (int ky = 0; ky < 3; ++ky) {
            float iv[6];
#pragma unroll
            for (int jj = 0; jj < 6; ++jj) iv[jj] = tile[(ly + ky) * 35 + lx + jj];
#pragma unroll
            for (int kx = 0; kx < 3; ++kx) {
                const float* wv = wb + (ky * 3 + kx) * 32;
#pragma unroll
                for (int c = 0; c < 8; ++c) {
                    float wf = wv[c];
#pragma unroll
                    for (int pp = 0; pp < 4; ++pp)
                        acc[c][pp] = fmaf(iv[kx + pp], wf, acc[c][pp]);
                }
            }
        }
    }

    const int oy = by + ly, ox0 = bx + lx;
    const bool top = (oy == 0), bot = (oy == H - 1);
#pragma unroll
    for (int c = 0; c < 8; ++c) {
        int cout = tg * 8 + c;
        float bvv = bg[cout];
        float base = sums[cout];
        if (top) base -= sums[32 + cout];
        if (bot) base -= sums[64 + cout];
        float4 o0, o1;
        float* p0 = &o0.x;
        float* p1 = &o1.x;
#pragma unroll
        for (int pp = 0; pp < 4; ++pp) {
            int ox = ox0 + pp;
            float loc = base;
            if (ox == 0) {
                loc -= sums[96 + cout];
                if (top) loc += sums[160 + cout];
                if (bot) loc += sums[224 + cout];
            }
            if (ox == W - 1) {
                loc -= sums[128 + cout];
                if (top) loc += sums[192 + cout];
                if (bot) loc += sums[256 + cout];
            }
            p0[pp] = fmaxf(acc[c][pp] + bvv, 0.f);
            p1[pp] = fmaxf(loc - acc[c][pp] + bvv, 0.f);
        }
        size_t off = ((size_t)(bb * 32 + cout)) * NPIX + (size_t)oy * W + ox0;
        *reinterpret_cast<float4*>(&out0[off]) = o0;
        *reinterpret_cast<float4*>(&out1[off]) = o1;
    }
}

// ---------------------------------------------------------------------------
// conv7 (cin=64 concat, cout=3, 0.5*tanh), round-1/12 proven kernel.
// ---------------------------------------------------------------------------
__global__ void __launch_bounds__(256) conv7_k(
    const float* __restrict__ x1, const float* __restrict__ x3,
    const float* __restrict__ wg, const float* __restrict__ bg,
    float* __restrict__ out, int accumulate)
{
    __shared__ float w_s[64 * 9 * 3];
    __shared__ float tile[34 * 35];
    const int t  = threadIdx.x;
    const int lx = (t & 7) << 2;
    const int ly = t >> 3;
    const int bx = blockIdx.x << 5;
    const int by = blockIdx.y << 5;
    const int bb = blockIdx.z;

    for (int i = t; i < 64 * 9 * 3; i += 256) {
        int cout = i % 3;
        int rem  = i / 3;
        int cin  = rem / 9, tap = rem - cin * 9;
        w_s[i] = wg[(cout * 64 + cin) * 9 + tap];
    }

    float acc[3][4];
#pragma unroll
    for (int c = 0; c < 3; c++)
#pragma unroll
        for (int pp = 0; pp < 4; pp++) acc[c][pp] = 0.f;

    for (int cin = 0; cin < 64; ++cin) {
        const float* ip = (cin < 32)
            ? x1 + ((size_t)(bb * 32 + cin)) * NPIX
            : x3 + ((size_t)(bb * 32 + cin - 32)) * NPIX;
        __syncthreads();
        for (int i = t; i < 34 * 34; i += 256) {
            int r = i / 34, c = i - r * 34;
            int gy = by - 1 + r, gx = bx - 1 + c;
            tile[r * 35 + c] =
                ((unsigned)gy < (unsigned)H && (unsigned)gx < (unsigned)W)
                    ? ip[gy * W + gx] : 0.f;
        }
        __syncthreads();
        const float* wb = &w_s[cin * 27];
#pragma unroll
        for (int ky = 0; ky < 3; ++ky) {
            float iv[6];
#pragma unroll
            for (int jj = 0; jj < 6; ++jj) iv[jj] = tile[(ly + ky) * 35 + lx + jj];
#pragma unroll
            for (int kx = 0; kx < 3; ++kx) {
                const float* wv = wb + (ky * 3 + kx) * 3;
#pragma unroll
                for (int c = 0; c < 3; ++c) {
                    float wf = wv[c];
#pragma unroll
                    for (int pp = 0; pp < 4; ++pp)
                        acc[c][pp] = fmaf(iv[kx + pp], wf, acc[c][pp]);
                }
            }
        }
    }

    const int oy = by + ly, ox = bx + lx;
#pragma unroll
    for (int c = 0; c < 3; ++c) {
        float bv = bg[c];
        float4 o;
        o.x = 0.5f * tanhf(acc[c][0] + bv);
        o.y = 0.5f * tanhf(acc[c][1] + bv);
        o.z = 0.5f * tanhf(acc[c][2] + bv);
        o.w = 0.5f * tanhf(acc[c][3] + bv);
        float4* op = reinterpret_cast<float4*>(
            &out[((size_t)(bb * 3 + c)) * NPIX + oy * W + ox]);
        if (accumulate) {
            float4 prev = *op;
            o.x += prev.x; o.y += prev.y; o.z += prev.z; o.w += prev.w;
        }
        *op = o;
    }
}

// ---------------------------------------------------------------------------
// Fused refinement update + last-block finalize (single launch per iter).
// Deterministic: final 1024-entry sum done by ONE block in fixed order.
// Counters self-reset for graph replay.
// ---------------------------------------------------------------------------
__global__ void update_k(const float4* __restrict__ xin, float4* __restrict__ x,
                         const float4* __restrict__ xr, int it, int first)
{
    const bool active = it < g_b;
    if (!active && !first) return;
    float m  = g_sum[it] * (1.0f / (float)NXi);
    float cf = (0.63f - m) / (g_n3 - m);
    const int n4 = NXi / 4;
    float s = 0.f;
    for (int i = blockIdx.x * 512 + threadIdx.x; i < n4; i += gridDim.x * 512) {
        float4 xv = first ? xin[i] : x[i];
        if (active) {
            float4 rv = xr[i];
            xv.x += rv.x * (xv.x * xv.x - xv.x) * cf;
            xv.y += rv.y * (xv.y * xv.y - xv.y) * cf;
            xv.z += rv.z * (xv.z * xv.z - xv.z) * cf;
            xv.w += rv.w * (xv.w * xv.w - xv.w) * cf;
            x[i] = xv;
        } else {
            x[i] = xv;
        }
        s += (xv.x + xv.y) + (xv.z + xv.w);
    }
#pragma unroll
    for (int o = 16; o; o >>= 1) s += __shfl_xor_sync(0xffffffffu, s, o);
    __shared__ float ws[16];
    __shared__ int last;
    if ((threadIdx.x & 31) == 0) ws[threadIdx.x >> 5] = s;
    __syncthreads();
    if (threadIdx.x < 32) {
        s = (threadIdx.x < 16) ? ws[threadIdx.x] : 0.f;
#pragma unroll
        for (int o = 8; o; o >>= 1) s += __shfl_xor_sync(0xffffffffu, s, o);
        if (threadIdx.x == 0) {
            g_part[blockIdx.x] = s;
            __threadfence();
            unsigned old = atomicAdd(&g_cnt[it], 1u);
            last = (old == gridDim.x - 1) ? 1 : 0;
        }
    }
    __syncthreads();
    if (last) {
        // final reduction by the last-arriving block, fixed order
        __threadfence();
        float f = 0.f;
        for (int i = threadIdx.x; i < UBLOCKS; i += 512) f += g_part[i];
#pragma unroll
        for (int o = 16; o; o >>= 1) f += __shfl_xor_sync(0xffffffffu, f, o);
        if ((threadIdx.x & 31) == 0) ws[threadIdx.x >> 5] = f;
        __syncthreads();
        if (threadIdx.x == 0) {
            float tt = 0.f;
#pragma unroll
            for (int i = 0; i < 16; i++) tt += ws[i];
            g_sum[it + 1] = tt;
            g_cnt[it] = 0;            // reset for next graph replay
        }
    }
}

// ---------------------------------------------------------------------------
static constexpr int WINO4_SMEM = 20736 * 4;   // 82,944 B

extern "C" void kernel_launch(void* const* d_in, const int* in_sizes, int n_in,
                              void* d_out, int out_size)
{
    const float* x  = (const float*)d_in[0];
    const float* w1 = (const float*)d_in[1];
    const float* b1 = (const float*)d_in[2];
    const float* w2 = (const float*)d_in[3];
    const float* b2 = (const float*)d_in[4];
    const float* w3 = (const float*)d_in[5];
    const float* b3 = (const float*)d_in[6];
    const float* w7 = (const float*)d_in[7];
    const float* b7 = (const float*)d_in[8];

    float* xo = (float*)d_out;      // final x
    float* xr = xo + NXi;           // x_r

    float *px1, *px1b, *px2, *px3;
    cudaGetSymbolAddress((void**)&px1, g_x1);
    cudaGetSymbolAddress((void**)&px1b, g_x1b);
    cudaGetSymbolAddress((void**)&px2, g_x2);
    cudaGetSymbolAddress((void**)&px3, g_x3);

    cudaFuncSetAttribute(wino4_k, cudaFuncAttributeMaxDynamicSharedMemorySize,
                         WINO4_SMEM);

    dim3 cg1(16, 64, 8);       // conv1: 32x8 px tiles, 256 thr
    dim3 cgw(4, 128, 8);       // wino4: 2 sub-tiles of 64x * 4y px, 576 thr
    dim3 cg7(16, 16, 8);       // conv7: 32x32 px tiles, 256 thr

    // Round-12 proven launch structure; wino4 is the 4th launch (ncu slot).
    wino_wt4_k<<<2, 1024>>>(w2, w3);                            // 1
    conv1b_k<<<cg1, 256>>>(x, w1, b1, px1, px1b);               // 2
    reduce1_k<<<RBLOCKS, 256>>>(x);                             // 3
    wino4_k<<<cgw, 576, WINO4_SMEM>>>(px1, 0, b2, px2);         // 4  <- profiled
    wino4_k<<<cgw, 576, WINO4_SMEM>>>(px2, 1, b3, px3);         // 5
    conv7_k<<<cg7, 256>>>(px1, px3, w7, b7, xr, 0);             // 6
    reduce2_k<<<1, 256>>>();                                    // 7
    params_k<<<1, 1>>>();                                       // 8

    // branch 1 (input 1-x), conv1 output already in px1b
    wino4_k<<<cgw, 576, WINO4_SMEM>>>(px1b, 0, b2, px2);
    wino4_k<<<cgw, 576, WINO4_SMEM>>>(px2, 1, b3, px3);
    conv7_k<<<cg7, 256>>>(px1b, px3, w7, b7, xr, 2);

    for (int it = 0; it < MAXB; ++it) {
        update_k<<<UBLOCKS, 512>>>((const float4*)x, (float4*)xo,
                                   (const float4*)xr, it, it == 0 ? 1 : 0);
    }
}

// round 16
// speedup vs baseline: 1.1010x; 1.0562x over previous
#include <cuda_runtime.h>
#include <cmath>
#include <cstdint>

static constexpr int H = 512, W = 512, BATCH = 8;
static constexpr int NPIX = H * W;
static constexpr int NXi = BATCH * 3 * NPIX;          // 6,291,456
static constexpr int NFEAT = BATCH * 32 * NPIX;       // 67,108,864
static constexpr int MAXB = 10;                       // int(b) <= 10 always
static constexpr int RBLOCKS = 512;
static constexpr int UBLOCKS = 1024;

__device__ float g_x1[NFEAT];
__device__ float g_x1b[NFEAT];
__device__ float g_x2[NFEAT];
__device__ float g_x3[NFEAT];
__device__ float g_U4[2 * 36864];     // F(4x4,3x3) transformed w2, w3
__device__ float g_part[UBLOCKS];
__device__ float g_sum[MAXB + 2];
__device__ float g_n3;
__device__ int   g_b;
__device__ unsigned g_cnt[MAXB + 1];  // zero-init; self-resetting per replay

// ---------------------------------------------------------------------------
// Initial mean reduction + params (round-12 proven)
// ---------------------------------------------------------------------------
__global__ void reduce1_k(const float* __restrict__ x) {
    const float4* x4 = reinterpret_cast<const float4*>(x);
    const int n4 = NXi / 4;
    float s = 0.f;
    for (int i = blockIdx.x * 256 + threadIdx.x; i < n4; i += gridDim.x * 256) {
        float4 v = x4[i];
        s += (v.x + v.y) + (v.z + v.w);
    }
#pragma unroll
    for (int o = 16; o; o >>= 1) s += __shfl_xor_sync(0xffffffffu, s, o);
    __shared__ float ws[8];
    if ((threadIdx.x & 31) == 0) ws[threadIdx.x >> 5] = s;
    __syncthreads();
    if (threadIdx.x < 32) {
        s = (threadIdx.x < 8) ? ws[threadIdx.x] : 0.f;
#pragma unroll
        for (int o = 4; o; o >>= 1) s += __shfl_xor_sync(0xffffffffu, s, o);
        if (threadIdx.x == 0) g_part[blockIdx.x] = s;
    }
}

__global__ void reduce2_k() {
    float s = 0.f;
    for (int i = threadIdx.x; i < RBLOCKS; i += 256) s += g_part[i];
#pragma unroll
    for (int o = 16; o; o >>= 1) s += __shfl_xor_sync(0xffffffffu, s, o);
    __shared__ float ws[8];
    if ((threadIdx.x & 31) == 0) ws[threadIdx.x >> 5] = s;
    __syncthreads();
    if (threadIdx.x == 0) {
        float t = 0.f;
#pragma unroll
        for (int i = 0; i < 8; i++) t += ws[i];
        g_sum[0] = t;
    }
}

__global__ void params_k() {
    float m32 = g_sum[0] / (float)NXi;
    double xx1 = (double)m32;
    double s = xx1 * xx1;
    double n3 = -0.79 * s + 0.81 * xx1 + 1.4;
    double bf;
    if (xx1 < 0.1)       bf = -25.0 * xx1 + 10.0;
    else if (xx1 < 0.45) bf = 17.14 * s - 15.14 * xx1 + 10.0;
    else                 bf = 5.66 * s - 2.93 * xx1 + 7.2;
    g_n3 = (float)n3;
    int b = (int)bf;
    if (b > MAXB) b = MAXB;
    g_b = b;
}

// ---------------------------------------------------------------------------
// F(4x4,3x3) weight transform (round-12 proven).
// ---------------------------------------------------------------------------
__global__ void wino_wt4_k(const float* __restrict__ w2,
                           const float* __restrict__ w3) {
    const float* w = blockIdx.x ? w3 : w2;
    float* U = g_U4 + blockIdx.x * 36864;
    const float f6 = 1.f / 6.f, f12 = 1.f / 12.f, f24 = 1.f / 24.f;
    int t = threadIdx.x;
    int cout = t >> 5, cin = t & 31;
    float g[9];
#pragma unroll
    for (int i = 0; i < 9; i++) g[i] = w[(cout * 32 + cin) * 9 + i];
    float T[6][3];
#pragma unroll
    for (int c = 0; c < 3; c++) {
        float g0 = g[c], g1 = g[3 + c], g2 = g[6 + c];
        T[0][c] = 0.25f * g0;
        T[1][c] = -f6 * (g0 + g1 + g2);
        T[2][c] = f6 * (-g0 + g1 - g2);
        T[3][c] = f24 * g0 + f12 * g1 + f6 * g2;
        T[4][c] = f24 * g0 - f12 * g1 + f6 * g2;
        T[5][c] = g2;
    }
#pragma unroll
    for (int i = 0; i < 6; i++) {
        float t0 = T[i][0], t1 = T[i][1], t2 = T[i][2];
        float u[6];
        u[0] = 0.25f * t0;
        u[1] = -f6 * (t0 + t1 + t2);
        u[2] = f6 * (-t0 + t1 - t2);
        u[3] = f24 * t0 + f12 * t1 + f6 * t2;
        u[4] = f24 * t0 - f12 * t1 + f6 * t2;
        u[5] = t2;
#pragma unroll
        for (int j = 0; j < 6; j++)
            U[(i * 6 + j) * 1024 + cin * 32 + cout] = u[j];
    }
}

#define BT6(o0, o1, o2, o3, o4, o5, d0, d1, d2, d3, d4, d5) do {             \
        o0 = 4.f * d0 - 5.f * d2 + d4;                                       \
        o1 = -4.f * d1 - 4.f * d2 + d3 + d4;                                 \
        o2 = 4.f * d1 - 4.f * d2 - d3 + d4;                                  \
        o3 = -2.f * d1 - d2 + 2.f * d3 + d4;                                 \
        o4 = 2.f * d1 - d2 - 2.f * d3 + d4;                                  \
        o5 = 4.f * d1 - 5.f * d3 + d5;                                       \
    } while (0)

// ---------------------------------------------------------------------------
// Fused Winograd F(4x4,3x3) conv 32->32, bias+relu (round-12 core).
// v2: division-free staging — thread t<396 owns slot (r,c) with hoisted
// predicates; cin loop is pure pointer strides (same coalescing as before).
// ---------------------------------------------------------------------------
__global__ void __launch_bounds__(576, 2) wino4_k(
    const float* __restrict__ in, int usel,
    const float* __restrict__ bg, float* __restrict__ out)
{
    extern __shared__ float sm[];
    float* raw = sm;                  // 32 * 408
    float* T   = sm + 13056;          // 4 * 600
    float* V   = sm + 15456;          // 2 * 2304
    float* M   = sm;                  // alias, 36 * 576

    const int t = threadIdx.x;
    const int y0 = blockIdx.y << 2, bb = blockIdx.z;

    const int xc = t / 96;
    const int xrem = t - xc * 96;
    const int xtile = xrem / 6, xj = xrem - xtile * 6;
    const bool xact = (t < 384);

    const int p  = t >> 4;
    const int kk = t & 15;
    const int cg = kk & 3;
    const int tg = kk >> 2;
    const float* Ub = g_U4 + usel * 36864 + p * 1024 + cg * 8;

    const int eco = t & 31, etl = (t >> 5) & 15;
    const float bv = __ldg(&bg[eco]);
    float* plane = out + ((size_t)(bb * 32 + eco)) * NPIX;
    const float* inb = in + (size_t)bb * 32 * NPIX;

    // ---- staging identity (hoisted; t < 396 active) ----
    const int st_r = t / 66;              // 0..5 when active
    const int st_c = t - st_r * 66;       // 0..65
    const int st_gy = y0 - 1 + st_r;
    const bool st_act = (t < 396);
    const bool st_oky = st_act && ((unsigned)st_gy < (unsigned)H);
    float* const st_dst = raw + st_r * 68 + st_c;

#define STAGE1(g) do { if (xact) {                                           \
        const float* dp = raw + ((g) * 4 + xc) * 408 + xtile * 4 + xj;       \
        float d0 = dp[0], d1 = dp[68], d2 = dp[136];                         \
        float d3 = dp[204], d4 = dp[272], d5 = dp[340];                      \
        float* tp = T + xc * 600 + xtile * 37 + xj;                          \
        float o0, o1, o2, o3, o4, o5;                                        \
        BT6(o0, o1, o2, o3, o4, o5, d0, d1, d2, d3, d4, d5);                 \
        tp[0] = o0; tp[6] = o1; tp[12] = o2;                                 \
        tp[18] = o3; tp[24] = o4; tp[30] = o5;                               \
    } } while (0)

#define STAGE2(g) do { if (xact) {                                           \
        const float* tp = T + xc * 600 + xtile * 37 + xj * 6;                \
        float d0 = tp[0], d1 = tp[1], d2 = tp[2];                            \
        float d3 = tp[3], d4 = tp[4], d5 = tp[5];                            \
        float* vb = V + ((g) & 1) * 2304 + xc * 576 + xj * 96 + xtile;       \
        float o0, o1, o2, o3, o4, o5;                                        \
        BT6(o0, o1, o2, o3, o4, o5, d0, d1, d2, d3, d4, d5);                 \
        vb[0] = o0; vb[16] = o1; vb[32] = o2;                                \
        vb[48] = o3; vb[64] = o4; vb[80] = o5;                               \
    } } while (0)

#pragma unroll 1
    for (int tix = 0; tix < 2; ++tix) {
        const int x0 = ((blockIdx.x << 1) + tix) << 6;

        // ---- staging: division-free, predicates hoisted ----
        {
            const int gx = x0 - 1 + st_c;
            const bool ok = st_oky && ((unsigned)gx < (unsigned)W);
            const float* src = inb + (ok ? (size_t)st_gy * W + gx : 0);
            if (st_act) {
#pragma unroll 8
                for (int cin = 0; cin < 32; ++cin) {
                    float v = src[(size_t)cin * NPIX];
                    st_dst[cin * 408] = ok ? v : 0.f;
                }
            }
        }
        __syncthreads();

        float acc[8][4];
#pragma unroll
        for (int i = 0; i < 8; i++)
#pragma unroll
            for (int j = 0; j < 4; j++) acc[i][j] = 0.f;

        STAGE1(0);
        __syncthreads();
        STAGE2(0);
        __syncthreads();

#pragma unroll 1
        for (int g = 0; g < 8; ++g) {
            if (g < 7) STAGE1(g + 1);
            {
                const float* vb = V + (g & 1) * 2304 + p * 16 + tg * 4;
                const float* ub = Ub + g * 128;
#pragma unroll
                for (int cc = 0; cc < 4; ++cc) {
                    float4 u0 = __ldg(reinterpret_cast<const float4*>(ub + cc * 32));
                    float4 u1 = __ldg(reinterpret_cast<const float4*>(ub + cc * 32 + 4));
                    float4 v = *reinterpret_cast<const float4*>(vb + cc * 576);
                    float ua[8] = {u0.x, u0.y, u0.z, u0.w, u1.x, u1.y, u1.z, u1.w};
                    float va[4] = {v.x, v.y, v.z, v.w};
#pragma unroll
                    for (int c = 0; c < 8; c++) {
                        acc[c][0] = fmaf(ua[c], va[0], acc[c][0]);
                        acc[c][1] = fmaf(ua[c], va[1], acc[c][1]);
                        acc[c][2] = fmaf(ua[c], va[2], acc[c][2]);
                        acc[c][3] = fmaf(ua[c], va[3], acc[c][3]);
                    }
                }
            }
            __syncthreads();
            if (g < 7) STAGE2(g + 1);
            __syncthreads();
        }

#pragma unroll
        for (int ti = 0; ti < 4; ++ti) {
            float* mp = M + p * 576 + (tg * 4 + ti) * 36 + cg * 8;
            *reinterpret_cast<float4*>(mp) =
                make_float4(acc[0][ti], acc[1][ti], acc[2][ti], acc[3][ti]);
            *reinterpret_cast<float4*>(mp + 4) =
                make_float4(acc[4][ti], acc[5][ti], acc[6][ti], acc[7][ti]);
        }
        __syncthreads();

        if (t < 512) {
            const float* mb = M + etl * 36 + eco;
            float P[4][6];
#pragma unroll
            for (int j = 0; j < 6; ++j) {
                float c0 = mb[j * 576];
                float c1 = mb[(6 + j) * 576];
                float c2 = mb[(12 + j) * 576];
                float c3 = mb[(18 + j) * 576];
                float c4 = mb[(24 + j) * 576];
                float c5 = mb[(30 + j) * 576];
                P[0][j] = c0 + c1 + c2 + c3 + c4;
                P[1][j] = c1 - c2 + 2.f * c3 - 2.f * c4;
                P[2][j] = c1 + c2 + 4.f * c3 + 4.f * c4;
                P[3][j] = c1 - c2 + 8.f * c3 - 8.f * c4 + c5;
            }
            float* ob = plane + (size_t)y0 * W + x0 + etl * 4;
#pragma unroll
            for (int a = 0; a < 4; ++a) {
                float p0 = P[a][0], p1 = P[a][1], p2 = P[a][2];
                float p3 = P[a][3], p4 = P[a][4], p5 = P[a][5];
                float4 y;
                y.x = fmaxf(p0 + p1 + p2 + p3 + p4 + bv, 0.f);
                y.y = fmaxf(p1 - p2 + 2.f * p3 - 2.f * p4 + bv, 0.f);
                y.z = fmaxf(p1 + p2 + 4.f * p3 + 4.f * p4 + bv, 0.f);
                y.w = fmaxf(p1 - p2 + 8.f * p3 - 8.f * p4 + p5 + bv, 0.f);
                *reinterpret_cast<float4*>(ob + (size_t)a * W) = y;
            }
        }
        __syncthreads();
    }
#undef STAGE1
#undef STAGE2
}

// ---------------------------------------------------------------------------
// conv1 BOTH branches in one pass (round-10/12 proven).
// ---------------------------------------------------------------------------
__global__ void __launch_bounds__(256) conv1b_k(
    const float* __restrict__ in, const float* __restrict__ wg,
    const float* __restrict__ bg, float* __restrict__ out0,
    float* __restrict__ out1)
{
    __shared__ float w_s[3 * 9 * 32];
    __shared__ float sums[9 * 32];
    __shared__ float tile[10 * 35];
    const int t  = threadIdx.x;
    const int tg = t >> 6;
    const int pt = t & 63;
    const int lx = (pt & 7) << 2;
    const int ly = pt >> 3;
    const int bx = blockIdx.x << 5;
    const int by = blockIdx.y << 3;
    const int bb = blockIdx.z;

    for (int i = t; i < 3 * 9 * 32; i += 256) {
        int cout = i & 31;
        int rem  = i >> 5;
        int cin  = rem / 9, tap = rem - cin * 9;
        w_s[cin * 288 + tap * 32 + cout] = wg[(cout * 3 + cin) * 9 + tap];
    }
    __syncthreads();
    if (t < 32) {
        float TS = 0, R0 = 0, R2 = 0, C0 = 0, C2 = 0;
        float Wa = 0, Wb = 0, Wc = 0, Wd = 0;
        for (int cin = 0; cin < 3; ++cin) {
            const float* wb = &w_s[cin * 288];
            float w[9];
#pragma unroll
            for (int k = 0; k < 9; ++k) w[k] = wb[k * 32 + t];
            TS += w[0] + w[1] + w[2] + w[3] + w[4] + w[5] + w[6] + w[7] + w[8];
            R0 += w[0] + w[1] + w[2];
            R2 += w[6] + w[7] + w[8];
            C0 += w[0] + w[3] + w[6];
            C2 += w[2] + w[5] + w[8];
            Wa += w[0]; Wb += w[2]; Wc += w[6]; Wd += w[8];
        }
        sums[t]        = TS;
        sums[32 + t]   = R0;
        sums[64 + t]   = R2;
        sums[96 + t]   = C0;
        sums[128 + t]  = C2;
        sums[160 + t]  = Wa;
        sums[192 + t]  = Wb;
        sums[224 + t]  = Wc;
        sums[256 + t]  = Wd;
    }

    float acc[8][4];
#pragma unroll
    for (int c = 0; c < 8; c++)
#pragma unroll
        for (int pp = 0; pp < 4; pp++) acc[c][pp] = 0.f;

    const float* inb = in + (size_t)bb * 3 * NPIX;

    for (int cin = 0; cin < 3; ++cin) {
        __syncthreads();
        const float* ip = inb + (size_t)cin * NPIX;
        for (int i = t; i < 340; i += 256) {
            int r = i / 34, c = i - r * 34;
            int gy = by - 1 + r, gx = bx - 1 + c;
            float v = 0.f;
            if ((unsigned)gy < (unsigned)H && (unsigned)gx < (unsigned)W)
                v = ip[gy * W + gx];
            tile[r * 35 + c] = v;
        }
        __syncthreads();
        const float* wb = &w_s[cin * 288 + tg * 8];
#pragma unroll
        for (int ky = 0; ky < 3; ++ky) {
            float iv[6];
#pragma unroll
            for (int jj = 0; jj < 6; ++jj) iv[jj] = tile[(ly + ky) * 35 + lx + jj];
#pragma unroll
            for (int kx = 0; kx < 3; ++kx) {
                const float* wv = wb + (ky * 3 + kx) * 32;
#pragma unroll
                for (int c = 0; c < 8; ++c) {
                    float wf = wv[c];
#pragma unroll
                    for (int pp = 0; pp < 4; ++pp)
                        acc[c][pp] = fmaf(iv[kx + pp], wf, acc[c][pp]);
                }
            }
        }
    }

    const int oy = by + ly, ox0 = bx + lx;
    const bool top = (oy == 0), bot = (oy == H - 1);
#pragma unroll
    for (int c = 0; c < 8; ++c) {
        int cout = tg * 8 + c;
        float bvv = bg[cout];
        float base = sums[cout];
        if (top) base -= sums[32 + cout];
        if (bot) base -= sums[64 + cout];
        float4 o0, o1;
        float* p0 = &o0.x;
        float* p1 = &o1.x;
#pragma unroll
        for (int pp = 0; pp < 4; ++pp) {
            int ox = ox0 + pp;
            float loc = base;
            if (ox == 0) {
                loc -= sums[96 + cout];
                if (top) loc += sums[160 + cout];
                if (bot) loc += sums[224 + cout];
            }
            if (ox == W - 1) {
                loc -= sums[128 + cout];
                if (top) loc += sums[192 + cout];
                if (bot) loc += sums[256 + cout];
            }
            p0[pp] = fmaxf(acc[c][pp] + bvv, 0.f);
            p1[pp] = fmaxf(loc - acc[c][pp] + bvv, 0.f);
        }
        size_t off = ((size_t)(bb * 32 + cout)) * NPIX + (size_t)oy * W + ox0;
        *reinterpret_cast<float4*>(&out0[off]) = o0;
        *reinterpret_cast<float4*>(&out1[off]) = o1;
    }
}

// ---------------------------------------------------------------------------
// conv7 (cin=64 concat, cout=3, 0.5*tanh), round-1/12 proven kernel.
// ---------------------------------------------------------------------------
__global__ void __launch_bounds__(256) conv7_k(
    const float* __restrict__ x1, const float* __restrict__ x3,
    const float* __restrict__ wg, const float* __restrict__ bg,
    float* __restrict__ out, int accumulate)
{
    __shared__ float w_s[64 * 9 * 3];
    __shared__ float tile[34 * 35];
    const int t  = threadIdx.x;
    const int lx = (t & 7) << 2;
    const int ly = t >> 3;
    const int bx = blockIdx.x << 5;
    const int by = blockIdx.y << 5;
    const int bb = blockIdx.z;

    for (int i = t; i < 64 * 9 * 3; i += 256) {
        int cout = i % 3;
        int rem  = i / 3;
        int cin  = rem / 9, tap = rem - cin * 9;
        w_s[i] = wg[(cout * 64 + cin) * 9 + tap];
    }

    float acc[3][4];
#pragma unroll
    for (int c = 0; c < 3; c++)
#pragma unroll
        for (int pp = 0; pp < 4; pp++) acc[c][pp] = 0.f;

    for (int cin = 0; cin < 64; ++cin) {
        const float* ip = (cin < 32)
            ? x1 + ((size_t)(bb * 32 + cin)) * NPIX
            : x3 + ((size_t)(bb * 32 + cin - 32)) * NPIX;
        __syncthreads();
        for (int i = t; i < 34 * 34; i += 256) {
            int r = i / 34, c = i - r * 34;
            int gy = by - 1 + r, gx = bx - 1 + c;
            tile[r * 35 + c] =
                ((unsigned)gy < (unsigned)H && (unsigned)gx < (unsigned)W)
                    ? ip[gy * W + gx] : 0.f;
        }
        __syncthreads();
        const float* wb = &w_s[cin * 27];
#pragma unroll
        for (int ky = 0; ky < 3; ++ky) {
            float iv[6];
#pragma unroll
            for (int jj = 0; jj < 6; ++jj) iv[jj] = tile[(ly + ky) * 35 + lx + jj];
#pragma unroll
            for (int kx = 0; kx < 3; ++kx) {
                const float* wv = wb + (ky * 3 + kx) * 3;
#pragma unroll
                for (int c = 0; c < 3; ++c) {
                    float wf = wv[c];
#pragma unroll
                    for (int pp = 0; pp < 4; ++pp)
                        acc[c][pp] = fmaf(iv[kx + pp], wf, acc[c][pp]);
                }
            }
        }
    }

    const int oy = by + ly, ox = bx + lx;
#pragma unroll
    for (int c = 0; c < 3; ++c) {
        float bv = bg[c];
        float4 o;
        o.x = 0.5f * tanhf(acc[c][0] + bv);
        o.y = 0.5f * tanhf(acc[c][1] + bv);
        o.z = 0.5f * tanhf(acc[c][2] + bv);
        o.w = 0.5f * tanhf(acc[c][3] + bv);
        float4* op = reinterpret_cast<float4*>(
            &out[((size_t)(bb * 3 + c)) * NPIX + oy * W + ox]);
        if (accumulate) {
            float4 prev = *op;
            o.x += prev.x; o.y += prev.y; o.z += prev.z; o.w += prev.w;
        }
        *op = o;
    }
}

// ---------------------------------------------------------------------------
// Fused refinement update + last-block finalize (round-15 proven).
// ---------------------------------------------------------------------------
__global__ void update_k(const float4* __restrict__ xin, float4* __restrict__ x,
                         const float4* __restrict__ xr, int it, int first)
{
    const bool active = it < g_b;
    if (!active && !first) return;
    float m  = g_sum[it] * (1.0f / (float)NXi);
    float cf = (0.63f - m) / (g_n3 - m);
    const int n4 = NXi / 4;
    float s = 0.f;
    for (int i = blockIdx.x * 512 + threadIdx.x; i < n4; i += gridDim.x * 512) {
        float4 xv = first ? xin[i] : x[i];
        if (active) {
            float4 rv = xr[i];
            xv.x += rv.x * (xv.x * xv.x - xv.x) * cf;
            xv.y += rv.y * (xv.y * xv.y - xv.y) * cf;
            xv.z += rv.z * (xv.z * xv.z - xv.z) * cf;
            xv.w += rv.w * (xv.w * xv.w - xv.w) * cf;
            x[i] = xv;
        } else {
            x[i] = xv;
        }
        s += (xv.x + xv.y) + (xv.z + xv.w);
    }
#pragma unroll
    for (int o = 16; o; o >>= 1) s += __shfl_xor_sync(0xffffffffu, s, o);
    __shared__ float ws[16];
    __shared__ int last;
    if ((threadIdx.x & 31) == 0) ws[threadIdx.x >> 5] = s;
    __syncthreads();
    if (threadIdx.x < 32) {
        s = (threadIdx.x < 16) ? ws[threadIdx.x] : 0.f;
#pragma unroll
        for (int o = 8; o; o >>= 1) s += __shfl_xor_sync(0xffffffffu, s, o);
        if (threadIdx.x == 0) {
            g_part[blockIdx.x] = s;
            __threadfence();
            unsigned old = atomicAdd(&g_cnt[it], 1u);
            last = (old == gridDim.x - 1) ? 1 : 0;
        }
    }
    __syncthreads();
    if (last) {
        __threadfence();
        float f = 0.f;
        for (int i = threadIdx.x; i < UBLOCKS; i += 512) f += g_part[i];
#pragma unroll
        for (int o = 16; o; o >>= 1) f += __shfl_xor_sync(0xffffffffu, f, o);
        if ((threadIdx.x & 31) == 0) ws[threadIdx.x >> 5] = f;
        __syncthreads();
        if (threadIdx.x == 0) {
            float tt = 0.f;
#pragma unroll
            for (int i = 0; i < 16; i++) tt += ws[i];
            g_sum[it + 1] = tt;
            g_cnt[it] = 0;            // reset for next graph replay
        }
    }
}

// ---------------------------------------------------------------------------
static constexpr int WINO4_SMEM = 20736 * 4;   // 82,944 B

extern "C" void kernel_launch(void* const* d_in, const int* in_sizes, int n_in,
                              void* d_out, int out_size)
{
    const float* x  = (const float*)d_in[0];
    const float* w1 = (const float*)d_in[1];
    const float* b1 = (const float*)d_in[2];
    const float* w2 = (const float*)d_in[3];
    const float* b2 = (const float*)d_in[4];
    const float* w3 = (const float*)d_in[5];
    const float* b3 = (const float*)d_in[6];
    const float* w7 = (const float*)d_in[7];
    const float* b7 = (const float*)d_in[8];

    float* xo = (float*)d_out;      // final x
    float* xr = xo + NXi;           // x_r

    float *px1, *px1b, *px2, *px3;
    cudaGetSymbolAddress((void**)&px1, g_x1);
    cudaGetSymbolAddress((void**)&px1b, g_x1b);
    cudaGetSymbolAddress((void**)&px2, g_x2);
    cudaGetSymbolAddress((void**)&px3, g_x3);

    cudaFuncSetAttribute(wino4_k, cudaFuncAttributeMaxDynamicSharedMemorySize,
                         WINO4_SMEM);

    dim3 cg1(16, 64, 8);       // conv1: 32x8 px tiles, 256 thr
    dim3 cgw(4, 128, 8);       // wino4: 2 sub-tiles of 64x * 4y px, 576 thr
    dim3 cg7(16, 16, 8);       // conv7: 32x32 px tiles, 256 thr

    // Round-12 proven launch structure; wino4 is the 4th launch (ncu slot).
    wino_wt4_k<<<2, 1024>>>(w2, w3);                            // 1
    conv1b_k<<<cg1, 256>>>(x, w1, b1, px1, px1b);               // 2
    reduce1_k<<<RBLOCKS, 256>>>(x);                             // 3
    wino4_k<<<cgw, 576, WINO4_SMEM>>>(px1, 0, b2, px2);         // 4  <- profiled
    wino4_k<<<cgw, 576, WINO4_SMEM>>>(px2, 1, b3, px3);         // 5
    conv7_k<<<cg7, 256>>>(px1, px3, w7, b7, xr, 0);             // 6
    reduce2_k<<<1, 256>>>();                                    // 7
    params_k<<<1, 1>>>();                                       // 8

    // branch 1 (input 1-x), conv1 output already in px1b
    wino4_k<<<cgw, 576, WINO4_SMEM>>>(px1b, 0, b2, px2);
    wino4_k<<<cgw, 576, WINO4_SMEM>>>(px2, 1, b3, px3);
    conv7_k<<<cg7, 256>>>(px1b, px3, w7, b7, xr, 2);

    for (int it = 0; it < MAXB; ++it) {
        update_k<<<UBLOCKS, 512>>>((const float4*)x, (float4*)xo,
                                   (const float4*)xr, it, it == 0 ? 1 : 0);
    }
}